// round 3
// baseline (speedup 1.0000x reference)
#include <cuda_runtime.h>

typedef unsigned long long ull;
#define DEVFN __device__ __forceinline__

#define TT 32
#define BB 2048
#define DD 64
#define MT 16
#define NTH 256
#define NCTA (BB / MT)
#define PITCH 20

#define OFF_W0T 0
#define OFF_W2T (OFF_W0T + 64*256)
#define OFF_B0  (OFF_W2T + 256*64)
#define OFF_B1  (OFF_B0 + 256)
#define OFF_B2  (OFF_B1 + 256)
#define OFF_TS  (OFF_B2 + 64)
#define OFF_Y   (OFF_TS + 32)
#define OFF_YT  (OFF_Y + 64*PITCH)
#define OFF_K   (OFF_YT + 64*PITCH)
#define OFF_H0  (OFF_K + 6*64*PITCH)
#define OFF_H1  (OFF_H0 + 256*PITCH)
#define SMEM_FLOATS (OFF_H1 + 256*PITCH)
#define SMEM_BYTES (SMEM_FLOATS * 4)

__device__ float g_W1T[(256 + 16) * 256];

__constant__ float c_A[30] = {
    0.f, 0.f, 0.f, 0.f, 0.f,
    0.2f, 0.f, 0.f, 0.f, 0.f,
    (float)(3.0/40.0), (float)(9.0/40.0), 0.f, 0.f, 0.f,
    (float)(44.0/45.0), (float)(-56.0/15.0), (float)(32.0/9.0), 0.f, 0.f,
    (float)(19372.0/6561.0), (float)(-25360.0/2187.0), (float)(64448.0/6561.0), (float)(-212.0/729.0), 0.f,
    (float)(9017.0/3168.0), (float)(-355.0/33.0), (float)(46732.0/5247.0), (float)(49.0/176.0), (float)(-5103.0/18656.0)
};
__constant__ float c_C6[6] = {0.f, 0.2f, 0.3f, 0.8f, (float)(8.0/9.0), 1.f};
__constant__ float c_B6[6] = {(float)(35.0/384.0), 0.f, (float)(500.0/1113.0),
                              (float)(125.0/192.0), (float)(-2187.0/6784.0), (float)(11.0/84.0)};

DEVFN ull dup2(float x) {
    ull r; unsigned xi = __float_as_uint(x);
    asm("mov.b64 %0, {%1, %1};" : "=l"(r) : "r"(xi));
    return r;
}
DEVFN void fma2(ull& d, ull a, ull b) {
    asm("fma.rn.f32x2 %0, %1, %2, %0;" : "+l"(d) : "l"(a), "l"(b));
}
DEVFN void unpk(ull v, float& lo, float& hi) {
    unsigned a, b;
    asm("mov.b64 {%0, %1}, %2;" : "=r"(a), "=r"(b) : "l"(v));
    lo = __uint_as_float(a); hi = __uint_as_float(b);
}
DEVFN float fast_tanh(float x) {
    float ax = fabsf(x);
    float e  = __expf(-2.0f * ax);
    float r  = __fdividef(1.0f - e, 1.0f + e);
    return copysignf(r, x);
}

DEVFN void gstep(ull (&acc)[8], float bval, const float* pa) {
    ull bb = dup2(bval);
    ulonglong2 a0 = *reinterpret_cast<const ulonglong2*>(pa);
    ulonglong2 a1 = *reinterpret_cast<const ulonglong2*>(pa + 4);
    ulonglong2 a2 = *reinterpret_cast<const ulonglong2*>(pa + 8);
    ulonglong2 a3 = *reinterpret_cast<const ulonglong2*>(pa + 12);
    fma2(acc[0], a0.x, bb); fma2(acc[1], a0.y, bb);
    fma2(acc[2], a1.x, bb); fma2(acc[3], a1.y, bb);
    fma2(acc[4], a2.x, bb); fma2(acc[5], a2.y, bb);
    fma2(acc[6], a3.x, bb); fma2(acc[7], a3.y, bb);
}

// kout = (tanh(tanh(aIn@W0T + b0)@W1T + b1)@W2T + b2) * exp(tstage)
DEVFN void vf_eval(float* sm, float tstage, const float* aIn, float* kout, int tid) {
    float et = expf(tstage);

    {   // GEMM0 -> h0
        ull acc[8];
#pragma unroll
        for (int p = 0; p < 8; ++p) acc[p] = 0ull;
        const float* pb = sm + OFF_W0T + tid;
#pragma unroll 4
        for (int k = 0; k < 64; ++k)
            gstep(acc, pb[k * 256], aIn + k * PITCH);
        float bj = sm[OFF_B0 + tid];
        float* hd = sm + OFF_H0 + tid * PITCH;
#pragma unroll
        for (int p = 0; p < 8; ++p) {
            float v0, v1; unpk(acc[p], v0, v1);
            hd[2 * p]     = fast_tanh(v0 + bj);
            hd[2 * p + 1] = fast_tanh(v1 + bj);
        }
    }
    __syncthreads();

    {   // GEMM1 -> h1 (W1T streamed from L2, double-buffered)
        ull acc[8];
#pragma unroll
        for (int p = 0; p < 8; ++p) acc[p] = 0ull;
        const float* pb = g_W1T + tid;
        const float* pa = sm + OFF_H0;
        float bufA[8], bufB[8];
#pragma unroll
        for (int kk = 0; kk < 8; ++kk) bufA[kk] = pb[kk * 256];
        pb += 2048;
#pragma unroll 1
        for (int kc = 0; kc < 256; kc += 16) {
#pragma unroll
            for (int kk = 0; kk < 8; ++kk) bufB[kk] = pb[kk * 256];
            pb += 2048;
#pragma unroll
            for (int kk = 0; kk < 8; ++kk) gstep(acc, bufA[kk], pa + (kc + kk) * PITCH);
#pragma unroll
            for (int kk = 0; kk < 8; ++kk) bufA[kk] = pb[kk * 256];
            pb += 2048;
#pragma unroll
            for (int kk = 0; kk < 8; ++kk) gstep(acc, bufB[kk], pa + (kc + 8 + kk) * PITCH);
        }
        float bj = sm[OFF_B1 + tid];
        float* hd = sm + OFF_H1 + tid * PITCH;
#pragma unroll
        for (int p = 0; p < 8; ++p) {
            float v0, v1; unpk(acc[p], v0, v1);
            hd[2 * p]     = fast_tanh(v0 + bj);
            hd[2 * p + 1] = fast_tanh(v1 + bj);
        }
    }
    __syncthreads();

    {   // GEMM2 -> kout
        int d = tid & 63, q = tid >> 6;
        ull acc2[2]; acc2[0] = 0ull; acc2[1] = 0ull;
        const float* pb = sm + OFF_W2T + d;
        const float* pa = sm + OFF_H1 + 4 * q;
#pragma unroll 4
        for (int u = 0; u < 256; ++u) {
            ull bb = dup2(pb[u * 64]);
            ulonglong2 av = *reinterpret_cast<const ulonglong2*>(pa + u * PITCH);
            fma2(acc2[0], av.x, bb);
            fma2(acc2[1], av.y, bb);
        }
        float bd = sm[OFF_B2 + d];
        float v0, v1, v2, v3;
        unpk(acc2[0], v0, v1); unpk(acc2[1], v2, v3);
        float* kd = kout + d * PITCH + 4 * q;
        kd[0] = (v0 + bd) * et; kd[1] = (v1 + bd) * et;
        kd[2] = (v2 + bd) * et; kd[3] = (v3 + bd) * et;
    }
    __syncthreads();
}

__global__ void __launch_bounds__(NTH, 1)
prep_kernel(const float* __restrict__ W1, const float* __restrict__ y0,
            float* __restrict__ out) {
    int stride = gridDim.x * blockDim.x;
    int t0 = blockIdx.x * blockDim.x + threadIdx.x;
    for (int idx = t0; idx < 256 * 256; idx += stride) {
        int r = idx >> 8, c = idx & 255;
        g_W1T[c * 256 + r] = W1[idx];
    }
    for (int idx = t0; idx < 16 * 256; idx += stride)
        g_W1T[65536 + idx] = 0.f;
    for (int idx = t0; idx < BB * DD; idx += stride)
        out[idx] = y0[idx];
}

__global__ void __launch_bounds__(NTH, 1)
ode_kernel(const float* __restrict__ ts, const float* __restrict__ y0,
           const float* __restrict__ W0, const float* __restrict__ b0,
           const float* __restrict__ b1,
           const float* __restrict__ W2, const float* __restrict__ b2,
           float* __restrict__ out) {
    extern __shared__ float sm[];
    int tid = threadIdx.x;
    int r0 = blockIdx.x * MT;

    for (int idx = tid; idx < 64 * 256; idx += NTH) {
        int w = idx >> 6, d = idx & 63;
        sm[OFF_W0T + d * 256 + w] = W0[idx];
    }
    for (int idx = tid; idx < 64 * 256; idx += NTH) {
        int d = idx >> 8, u = idx & 255;
        sm[OFF_W2T + u * 64 + d] = W2[idx];
    }
    if (tid < 256) { sm[OFF_B0 + tid] = b0[tid]; sm[OFF_B1 + tid] = b1[tid]; }
    if (tid < 64)  sm[OFF_B2 + tid] = b2[tid];
    if (tid < 32)  sm[OFF_TS + tid] = ts[tid];
    for (int i = tid; i < MT * DD; i += NTH) {
        int d = i >> 4, m = i & 15;
        sm[OFF_Y + d * PITCH + m] = y0[(r0 + m) * DD + d];
    }
    __syncthreads();

    float* sY  = sm + OFF_Y;
    float* sYt = sm + OFF_YT;
    float* sK  = sm + OFF_K;

    for (int iv = 0; iv < TT - 1; ++iv) {
        float t0v = sm[OFF_TS + iv];
        float h   = 0.5f * (sm[OFF_TS + iv + 1] - t0v);
        for (int sub = 0; sub < 2; ++sub) {
            float tc = t0v + sub * h;
            for (int s = 0; s < 6; ++s) {
                const float* aIn = (s == 0) ? sY : sYt;
                vf_eval(sm, tc + h * c_C6[s], aIn, sK + s * 64 * PITCH, tid);
                if (s < 5) {
                    for (int i = tid; i < MT * DD; i += NTH) {
                        int d = i >> 4, m = i & 15;
                        int off = d * PITCH + m;
                        float acc = sY[off];
                        for (int j = 0; j <= s; ++j)
                            acc += h * c_A[(s + 1) * 5 + j] * sK[j * 64 * PITCH + off];
                        sYt[off] = acc;
                    }
                    __syncthreads();
                }
            }
            for (int i = tid; i < MT * DD; i += NTH) {
                int d = i >> 4, m = i & 15;
                int off = d * PITCH + m;
                float acc = sY[off];
                acc += h * (c_B6[0] * sK[0 * 64 * PITCH + off]
                          + c_B6[2] * sK[2 * 64 * PITCH + off]
                          + c_B6[3] * sK[3 * 64 * PITCH + off]
                          + c_B6[4] * sK[4 * 64 * PITCH + off]
                          + c_B6[5] * sK[5 * 64 * PITCH + off]);
                sY[off] = acc;
            }
            __syncthreads();
        }
        float* dst = out + (size_t)(iv + 1) * BB * DD + (size_t)r0 * DD;
        for (int i = tid; i < MT * DD; i += NTH) {
            int m = i >> 6, d = i & 63;
            dst[i] = sY[d * PITCH + m];
        }
    }
}

extern "C" void kernel_launch(void* const* d_in, const int* in_sizes, int n_in,
                              void* d_out, int out_size) {
    if (n_in < 8) return;
    const float* ts = (const float*)d_in[0];
    const float* y0 = (const float*)d_in[1];
    const float* W0 = (const float*)d_in[2];
    const float* b0 = (const float*)d_in[3];
    const float* W1 = (const float*)d_in[4];
    const float* b1 = (const float*)d_in[5];
    const float* W2 = (const float*)d_in[6];
    const float* b2 = (const float*)d_in[7];
    float* out = (float*)d_out;

    cudaFuncSetAttribute(ode_kernel, cudaFuncAttributeMaxDynamicSharedMemorySize, SMEM_BYTES);

    prep_kernel<<<256, NTH>>>(W1, y0, out);
    ode_kernel<<<NCTA, NTH, SMEM_BYTES>>>(ts, y0, W0, b0, b1, W2, b2, out);
}